// round 11
// baseline (speedup 1.0000x reference)
#include <cuda_runtime.h>
#include <cuda_bf16.h>
#include <cstdint>

// ---------------------------------------------------------------------------
// BatchChildSumTreeLSTM on GB300 (sm_103a)
// Levels processed bottom-up. Per level:
//   G = X @ [Wix|Wox|Wux|Wfx]   (X = emb[sen[level]])
//   A = H_child @ [Wih|Woh|Wuh|Wfh]
//   combine: gates + per-child forget + c/h update
// GEMMs: fp32 with packed fma.rn.f32x2 (Blackwell), 128x128 tiles, K=128.
// ---------------------------------------------------------------------------

#define HID 128

// level geometry
__host__ __device__ static const int LSH[6]  = {4096, 16384, 65536, 131072, 262144, 262144};
static const int OFFH[7] = {0, 4096, 20480, 86016, 217088, 479232, 741376};

// scratch (device globals -- no cudaMalloc allowed)
__device__ float g_G[262144ull * 512];      // 512 MB: parent-level gate pre-activations from x
__device__ float g_A[262144ull * 512];      // 512 MB: child-level gate pre-activations from h
__device__ float g_H[741376ull * 128];      // 380 MB
__device__ float g_C[741376ull * 128];      // 380 MB
__device__ float g_Wx[128 * 512];           // [k][ i | o | u | f ]  from x
__device__ float g_Wh[128 * 512];           // [k][ i | o | u | f ]  from h
__device__ float g_bias[512];               // folded b_*x + b_*h per gate

// ---------------------------------------------------------------------------
// f32x2 helpers
// ---------------------------------------------------------------------------
__device__ __forceinline__ unsigned long long pk2(float x, float y) {
    unsigned long long r;
    asm("mov.b64 %0, {%1, %2};" : "=l"(r) : "f"(x), "f"(y));
    return r;
}
__device__ __forceinline__ void fma2(unsigned long long& d, unsigned long long a, unsigned long long b) {
    asm("fma.rn.f32x2 %0, %1, %2, %0;" : "+l"(d) : "l"(a), "l"(b));
}
__device__ __forceinline__ void upk2(unsigned long long v, float& x, float& y) {
    asm("mov.b64 {%0, %1}, %2;" : "=f"(x), "=f"(y) : "l"(v));
}

__device__ __forceinline__ float sigmoidf_(float x) {
    return 1.0f / (1.0f + __expf(-x));
}
__device__ __forceinline__ float tanhf_(float x) {
    float ax = fabsf(x);
    float e  = __expf(-2.0f * ax);
    float t  = (1.0f - e) / (1.0f + e);
    return x < 0.0f ? -t : t;
}

// ---------------------------------------------------------------------------
// weight / bias packing:  g_Wx[k][gate*128+j], gates = {i, o, u, f}
// ---------------------------------------------------------------------------
__global__ void pack_weights(
    const float* __restrict__ Wix, const float* __restrict__ Wih,
    const float* __restrict__ Wfx, const float* __restrict__ Wfh,
    const float* __restrict__ Wox, const float* __restrict__ Woh,
    const float* __restrict__ Wux, const float* __restrict__ Wuh,
    const float* __restrict__ bix, const float* __restrict__ bih,
    const float* __restrict__ bfx, const float* __restrict__ bfh,
    const float* __restrict__ box_, const float* __restrict__ boh,
    const float* __restrict__ bux, const float* __restrict__ buh)
{
    int idx = blockIdx.x * blockDim.x + threadIdx.x;  // 65536 threads
    int k    = idx >> 9;
    int col  = idx & 511;
    int gate = col >> 7;
    int j    = col & 127;

    const float* wx;
    const float* wh;
    const float* bx;
    const float* bh;
    switch (gate) {
        case 0: wx = Wix; wh = Wih; bx = bix; bh = bih; break;
        case 1: wx = Wox; wh = Woh; bx = box_; bh = boh; break;
        case 2: wx = Wux; wh = Wuh; bx = bux; bh = buh; break;
        default: wx = Wfx; wh = Wfh; bx = bfx; bh = bfh; break;
    }
    g_Wx[idx] = wx[k * 128 + j];
    g_Wh[idx] = wh[k * 128 + j];
    if (k == 0) g_bias[col] = bx[j] + bh[j];
}

// ---------------------------------------------------------------------------
// GEMM: C[M,512] = A[M,128] @ B[128,512]
// BM=128, BN=128 (grid.y = 4 column tiles), K=128 single slab.
// A rows optionally gathered through an int index array (embedding lookup).
// 256 threads; thread tile 8x8 (two 4x4 quads), f32x2 accumulators.
// ---------------------------------------------------------------------------
#define AS_STRIDE 132
#define SMEM_FLOATS (128 * AS_STRIDE + 128 * 128)
#define SMEM_BYTES (SMEM_FLOATS * 4)

template <bool GATHER>
__global__ void __launch_bounds__(256)
gemm128(const float* __restrict__ Abase, const int* __restrict__ idx,
        const float* __restrict__ B, float* __restrict__ Cout)
{
    extern __shared__ float sm[];
    float* As = sm;                       // [m][k] natural, stride 132
    float* Bs = sm + 128 * AS_STRIDE;     // [k][n] stride 128

    const int tid = threadIdx.x;
    const size_t mBase = (size_t)blockIdx.x * 128;
    const int nBase = blockIdx.y * 128;

    // load B tile (row-major slice of [128,512])
    {
        int k = tid >> 5;
        int n = (tid & 31) * 4;
#pragma unroll
        for (int s = 0; s < 16; ++s, k += 8) {
            float4 v = *reinterpret_cast<const float4*>(B + k * 512 + nBase + n);
            *reinterpret_cast<float4*>(Bs + k * 128 + n) = v;
        }
    }
    // load A tile (optionally gathered); one warp streams one 512B row
    {
        int m = tid >> 5;
        int k4 = (tid & 31) * 4;
#pragma unroll
        for (int s = 0; s < 16; ++s, m += 8) {
            size_t row = mBase + m;
            const float* src;
            if (GATHER)
                src = Abase + (size_t)idx[row] * 128 + k4;
            else
                src = Abase + row * 128 + k4;
            float4 v = *reinterpret_cast<const float4*>(src);
            *reinterpret_cast<float4*>(As + m * AS_STRIDE + k4) = v;
        }
    }
    __syncthreads();

    const int tx = tid & 15, ty = tid >> 4;
    int rows[8];
#pragma unroll
    for (int r = 0; r < 4; ++r) { rows[r] = ty * 4 + r; rows[4 + r] = 64 + ty * 4 + r; }
    const int n0 = tx * 4, n1 = 64 + tx * 4;

    unsigned long long acc[8][4];
#pragma unroll
    for (int r = 0; r < 8; ++r) {
        acc[r][0] = 0ull; acc[r][1] = 0ull; acc[r][2] = 0ull; acc[r][3] = 0ull;
    }

#pragma unroll 2
    for (int kc = 0; kc < 128; kc += 4) {
        float a[8][4];
#pragma unroll
        for (int r = 0; r < 8; ++r) {
            float4 v = *reinterpret_cast<const float4*>(As + rows[r] * AS_STRIDE + kc);
            a[r][0] = v.x; a[r][1] = v.y; a[r][2] = v.z; a[r][3] = v.w;
        }
#pragma unroll
        for (int kk = 0; kk < 4; ++kk) {
            const int k = kc + kk;
            float4 b0 = *reinterpret_cast<const float4*>(Bs + k * 128 + n0);
            float4 b1 = *reinterpret_cast<const float4*>(Bs + k * 128 + n1);
            unsigned long long bb0 = pk2(b0.x, b0.y);
            unsigned long long bb1 = pk2(b0.z, b0.w);
            unsigned long long bb2 = pk2(b1.x, b1.y);
            unsigned long long bb3 = pk2(b1.z, b1.w);
#pragma unroll
            for (int r = 0; r < 8; ++r) {
                unsigned long long aa = pk2(a[r][kk], a[r][kk]);
                fma2(acc[r][0], aa, bb0);
                fma2(acc[r][1], aa, bb1);
                fma2(acc[r][2], aa, bb2);
                fma2(acc[r][3], aa, bb3);
            }
        }
    }

#pragma unroll
    for (int r = 0; r < 8; ++r) {
        size_t row = mBase + rows[r];
        float4 v, w;
        upk2(acc[r][0], v.x, v.y);
        upk2(acc[r][1], v.z, v.w);
        upk2(acc[r][2], w.x, w.y);
        upk2(acc[r][3], w.z, w.w);
        *reinterpret_cast<float4*>(Cout + row * 512 + nBase + n0) = v;
        *reinterpret_cast<float4*>(Cout + row * 512 + nBase + n1) = w;
    }
}

// ---------------------------------------------------------------------------
// combine: per (node, hid) element, fold child contributions + nonlinearities
// ---------------------------------------------------------------------------
__global__ void __launch_bounds__(256)
combine(const float* __restrict__ G, const float* __restrict__ A,
        const float* __restrict__ Cc, const float* __restrict__ bias,
        float* __restrict__ Hout, float* __restrict__ Cout,
        int ratio, int leaf)
{
    int idx = blockIdx.x * 256 + threadIdx.x;
    int p = idx >> 7;
    int j = idx & 127;
    size_t g = (size_t)p * 512 + j;

    float zi = G[g]       + bias[j];
    float zo = G[g + 128] + bias[128 + j];
    float zu = G[g + 256] + bias[256 + j];
    float fc = 0.0f;

    if (!leaf) {
        float gf = G[g + 384] + bias[384 + j];
        const float* Ap = A + (size_t)p * ratio * 512 + j;
        const float* Cp = Cc + (size_t)p * ratio * 128 + j;
        for (int t = 0; t < ratio; ++t) {
            zi += Ap[0];
            zo += Ap[128];
            zu += Ap[256];
            float f = sigmoidf_(gf + Ap[384]);
            fc += f * Cp[0];
            Ap += 512;
            Cp += 128;
        }
    }

    float i = sigmoidf_(zi);
    float o = sigmoidf_(zo);
    float u = tanhf_(zu);
    float c = i * u + fc;
    Hout[(size_t)p * 128 + j] = o * tanhf_(c);
    Cout[(size_t)p * 128 + j] = c;
}

// ---------------------------------------------------------------------------
// output head: out[4096,4] = H_root @ W_out + b_out  (one warp per row)
// ---------------------------------------------------------------------------
__global__ void out_kernel(const float* __restrict__ H,
                           const float* __restrict__ Wout,
                           const float* __restrict__ bout,
                           float* __restrict__ out)
{
    int warp = (blockIdx.x * blockDim.x + threadIdx.x) >> 5;
    int lane = threadIdx.x & 31;
    const float* h = H + (size_t)warp * 128;

    float s0 = 0.f, s1 = 0.f, s2 = 0.f, s3 = 0.f;
#pragma unroll
    for (int k = lane; k < 128; k += 32) {
        float hv = h[k];
        float4 w = *reinterpret_cast<const float4*>(Wout + k * 4);
        s0 += hv * w.x; s1 += hv * w.y; s2 += hv * w.z; s3 += hv * w.w;
    }
#pragma unroll
    for (int off = 16; off; off >>= 1) {
        s0 += __shfl_xor_sync(0xffffffffu, s0, off);
        s1 += __shfl_xor_sync(0xffffffffu, s1, off);
        s2 += __shfl_xor_sync(0xffffffffu, s2, off);
        s3 += __shfl_xor_sync(0xffffffffu, s3, off);
    }
    if (lane == 0) {
        float4 v = make_float4(s0 + bout[0], s1 + bout[1], s2 + bout[2], s3 + bout[3]);
        *reinterpret_cast<float4*>(out + (size_t)warp * 4) = v;
    }
}

// ---------------------------------------------------------------------------
// launch
// ---------------------------------------------------------------------------
extern "C" void kernel_launch(void* const* d_in, const int* in_sizes, int n_in,
                              void* d_out, int out_size)
{
    const int*   sen = (const int*)d_in[0];
    const float* emb = (const float*)d_in[1];
    const float* W_ix = (const float*)d_in[2];
    const float* b_ix = (const float*)d_in[3];
    const float* W_ih = (const float*)d_in[4];
    const float* b_ih = (const float*)d_in[5];
    const float* W_fx = (const float*)d_in[6];
    const float* b_fx = (const float*)d_in[7];
    const float* W_fh = (const float*)d_in[8];
    const float* b_fh = (const float*)d_in[9];
    const float* W_ox = (const float*)d_in[10];
    const float* b_ox = (const float*)d_in[11];
    const float* W_oh = (const float*)d_in[12];
    const float* b_oh = (const float*)d_in[13];
    const float* W_ux = (const float*)d_in[14];
    const float* b_ux = (const float*)d_in[15];
    const float* W_uh = (const float*)d_in[16];
    const float* b_uh = (const float*)d_in[17];
    const float* W_out = (const float*)d_in[18];
    const float* b_out = (const float*)d_in[19];
    float* out = (float*)d_out;

    float *G, *A, *H, *C, *Wx, *Wh, *bias;
    cudaGetSymbolAddress((void**)&G, g_G);
    cudaGetSymbolAddress((void**)&A, g_A);
    cudaGetSymbolAddress((void**)&H, g_H);
    cudaGetSymbolAddress((void**)&C, g_C);
    cudaGetSymbolAddress((void**)&Wx, g_Wx);
    cudaGetSymbolAddress((void**)&Wh, g_Wh);
    cudaGetSymbolAddress((void**)&bias, g_bias);

    cudaFuncSetAttribute(gemm128<true>, cudaFuncAttributeMaxDynamicSharedMemorySize, SMEM_BYTES);
    cudaFuncSetAttribute(gemm128<false>, cudaFuncAttributeMaxDynamicSharedMemorySize, SMEM_BYTES);

    pack_weights<<<256, 256>>>(W_ix, W_ih, W_fx, W_fh, W_ox, W_oh, W_ux, W_uh,
                               b_ix, b_ih, b_fx, b_fh, b_ox, b_oh, b_ux, b_uh);

    static const int OFFH_[7] = {0, 4096, 20480, 86016, 217088, 479232, 741376};
    static const int LSH_[6]  = {4096, 16384, 65536, 131072, 262144, 262144};

    for (int L = 5; L >= 0; --L) {
        const int o0 = OFFH_[L];
        const int nL = LSH_[L];

        // G = gather(emb, sen) @ Wx4
        gemm128<true><<<dim3(nL / 128, 4), 256, SMEM_BYTES>>>(emb, sen + o0, Wx, G);

        if (L < 5) {
            const int c0 = OFFH_[L + 1];
            const int nC = LSH_[L + 1];
            // A = H_child @ Wh4
            gemm128<false><<<dim3(nC / 128, 4), 256, SMEM_BYTES>>>(
                H + (size_t)c0 * 128, nullptr, Wh, A);
            combine<<<nL / 2, 256>>>(G, A, C + (size_t)c0 * 128, bias,
                                     H + (size_t)o0 * 128, C + (size_t)o0 * 128,
                                     nC / nL, 0);
        } else {
            combine<<<nL / 2, 256>>>(G, nullptr, nullptr, bias,
                                     H + (size_t)o0 * 128, C + (size_t)o0 * 128,
                                     0, 1);
        }
    }

    out_kernel<<<4096 / 8, 256>>>(H, W_out, b_out, out);
}

// round 12
// speedup vs baseline: 1.0012x; 1.0012x over previous
#include <cuda_runtime.h>
#include <cuda_bf16.h>
#include <cstdint>

// ---------------------------------------------------------------------------
// BatchChildSumTreeLSTM on GB300 (sm_103a)
// Levels processed bottom-up. Per level:
//   G = X @ [Wix|Wox|Wux|Wfx]   (X = emb[sen[level]])
//   A = H_child @ [Wih|Woh|Wuh|Wfh]
//   combine: gates + per-child forget + c/h update
// GEMMs: fp32 with packed fma.rn.f32x2 (Blackwell), 128x128 tiles, K=128.
// ---------------------------------------------------------------------------

#define HID 128

// level geometry
__host__ __device__ static const int LSH[6]  = {4096, 16384, 65536, 131072, 262144, 262144};
static const int OFFH[7] = {0, 4096, 20480, 86016, 217088, 479232, 741376};

// scratch (device globals -- no cudaMalloc allowed)
__device__ float g_G[262144ull * 512];      // 512 MB: parent-level gate pre-activations from x
__device__ float g_A[262144ull * 512];      // 512 MB: child-level gate pre-activations from h
__device__ float g_H[741376ull * 128];      // 380 MB
__device__ float g_C[741376ull * 128];      // 380 MB
__device__ float g_Wx[128 * 512];           // [k][ i | o | u | f ]  from x
__device__ float g_Wh[128 * 512];           // [k][ i | o | u | f ]  from h
__device__ float g_bias[512];               // folded b_*x + b_*h per gate

// ---------------------------------------------------------------------------
// f32x2 helpers
// ---------------------------------------------------------------------------
__device__ __forceinline__ unsigned long long pk2(float x, float y) {
    unsigned long long r;
    asm("mov.b64 %0, {%1, %2};" : "=l"(r) : "f"(x), "f"(y));
    return r;
}
__device__ __forceinline__ void fma2(unsigned long long& d, unsigned long long a, unsigned long long b) {
    asm("fma.rn.f32x2 %0, %1, %2, %0;" : "+l"(d) : "l"(a), "l"(b));
}
__device__ __forceinline__ void upk2(unsigned long long v, float& x, float& y) {
    asm("mov.b64 {%0, %1}, %2;" : "=f"(x), "=f"(y) : "l"(v));
}

__device__ __forceinline__ float sigmoidf_(float x) {
    return 1.0f / (1.0f + __expf(-x));
}
__device__ __forceinline__ float tanhf_(float x) {
    float ax = fabsf(x);
    float e  = __expf(-2.0f * ax);
    float t  = (1.0f - e) / (1.0f + e);
    return x < 0.0f ? -t : t;
}

// ---------------------------------------------------------------------------
// weight / bias packing:  g_Wx[k][gate*128+j], gates = {i, o, u, f}
// ---------------------------------------------------------------------------
__global__ void pack_weights(
    const float* __restrict__ Wix, const float* __restrict__ Wih,
    const float* __restrict__ Wfx, const float* __restrict__ Wfh,
    const float* __restrict__ Wox, const float* __restrict__ Woh,
    const float* __restrict__ Wux, const float* __restrict__ Wuh,
    const float* __restrict__ bix, const float* __restrict__ bih,
    const float* __restrict__ bfx, const float* __restrict__ bfh,
    const float* __restrict__ box_, const float* __restrict__ boh,
    const float* __restrict__ bux, const float* __restrict__ buh)
{
    int idx = blockIdx.x * blockDim.x + threadIdx.x;  // 65536 threads
    int k    = idx >> 9;
    int col  = idx & 511;
    int gate = col >> 7;
    int j    = col & 127;

    const float* wx;
    const float* wh;
    const float* bx;
    const float* bh;
    switch (gate) {
        case 0: wx = Wix; wh = Wih; bx = bix; bh = bih; break;
        case 1: wx = Wox; wh = Woh; bx = box_; bh = boh; break;
        case 2: wx = Wux; wh = Wuh; bx = bux; bh = buh; break;
        default: wx = Wfx; wh = Wfh; bx = bfx; bh = bfh; break;
    }
    g_Wx[idx] = wx[k * 128 + j];
    g_Wh[idx] = wh[k * 128 + j];
    if (k == 0) g_bias[col] = bx[j] + bh[j];
}

// ---------------------------------------------------------------------------
// GEMM: C[M,512] = A[M,128] @ B[128,512]
// BM=128, BN=128 (grid.y = 4 column tiles), K=128 single slab.
// A rows optionally gathered through an int index array (embedding lookup).
// 256 threads; thread tile 8x8 (two 4x4 quads), f32x2 accumulators.
// ---------------------------------------------------------------------------
#define AS_STRIDE 132
#define SMEM_FLOATS (128 * AS_STRIDE + 128 * 128)
#define SMEM_BYTES (SMEM_FLOATS * 4)

template <bool GATHER>
__global__ void __launch_bounds__(256)
gemm128(const float* __restrict__ Abase, const int* __restrict__ idx,
        const float* __restrict__ B, float* __restrict__ Cout)
{
    extern __shared__ float sm[];
    float* As = sm;                       // [m][k] natural, stride 132
    float* Bs = sm + 128 * AS_STRIDE;     // [k][n] stride 128

    const int tid = threadIdx.x;
    const size_t mBase = (size_t)blockIdx.x * 128;
    const int nBase = blockIdx.y * 128;

    // load B tile (row-major slice of [128,512])
    {
        int k = tid >> 5;
        int n = (tid & 31) * 4;
#pragma unroll
        for (int s = 0; s < 16; ++s, k += 8) {
            float4 v = *reinterpret_cast<const float4*>(B + k * 512 + nBase + n);
            *reinterpret_cast<float4*>(Bs + k * 128 + n) = v;
        }
    }
    // load A tile (optionally gathered); one warp streams one 512B row
    {
        int m = tid >> 5;
        int k4 = (tid & 31) * 4;
#pragma unroll
        for (int s = 0; s < 16; ++s, m += 8) {
            size_t row = mBase + m;
            const float* src;
            if (GATHER)
                src = Abase + (size_t)idx[row] * 128 + k4;
            else
                src = Abase + row * 128 + k4;
            float4 v = *reinterpret_cast<const float4*>(src);
            *reinterpret_cast<float4*>(As + m * AS_STRIDE + k4) = v;
        }
    }
    __syncthreads();

    const int tx = tid & 15, ty = tid >> 4;
    int rows[8];
#pragma unroll
    for (int r = 0; r < 4; ++r) { rows[r] = ty * 4 + r; rows[4 + r] = 64 + ty * 4 + r; }
    const int n0 = tx * 4, n1 = 64 + tx * 4;

    unsigned long long acc[8][4];
#pragma unroll
    for (int r = 0; r < 8; ++r) {
        acc[r][0] = 0ull; acc[r][1] = 0ull; acc[r][2] = 0ull; acc[r][3] = 0ull;
    }

#pragma unroll 2
    for (int kc = 0; kc < 128; kc += 4) {
        float a[8][4];
#pragma unroll
        for (int r = 0; r < 8; ++r) {
            float4 v = *reinterpret_cast<const float4*>(As + rows[r] * AS_STRIDE + kc);
            a[r][0] = v.x; a[r][1] = v.y; a[r][2] = v.z; a[r][3] = v.w;
        }
#pragma unroll
        for (int kk = 0; kk < 4; ++kk) {
            const int k = kc + kk;
            float4 b0 = *reinterpret_cast<const float4*>(Bs + k * 128 + n0);
            float4 b1 = *reinterpret_cast<const float4*>(Bs + k * 128 + n1);
            unsigned long long bb0 = pk2(b0.x, b0.y);
            unsigned long long bb1 = pk2(b0.z, b0.w);
            unsigned long long bb2 = pk2(b1.x, b1.y);
            unsigned long long bb3 = pk2(b1.z, b1.w);
#pragma unroll
            for (int r = 0; r < 8; ++r) {
                unsigned long long aa = pk2(a[r][kk], a[r][kk]);
                fma2(acc[r][0], aa, bb0);
                fma2(acc[r][1], aa, bb1);
                fma2(acc[r][2], aa, bb2);
                fma2(acc[r][3], aa, bb3);
            }
        }
    }

#pragma unroll
    for (int r = 0; r < 8; ++r) {
        size_t row = mBase + rows[r];
        float4 v, w;
        upk2(acc[r][0], v.x, v.y);
        upk2(acc[r][1], v.z, v.w);
        upk2(acc[r][2], w.x, w.y);
        upk2(acc[r][3], w.z, w.w);
        *reinterpret_cast<float4*>(Cout + row * 512 + nBase + n0) = v;
        *reinterpret_cast<float4*>(Cout + row * 512 + nBase + n1) = w;
    }
}

// ---------------------------------------------------------------------------
// combine: per (node, hid) element, fold child contributions + nonlinearities
// ---------------------------------------------------------------------------
__global__ void __launch_bounds__(256)
combine(const float* __restrict__ G, const float* __restrict__ A,
        const float* __restrict__ Cc, const float* __restrict__ bias,
        float* __restrict__ Hout, float* __restrict__ Cout,
        int ratio, int leaf)
{
    int idx = blockIdx.x * 256 + threadIdx.x;
    int p = idx >> 7;
    int j = idx & 127;
    size_t g = (size_t)p * 512 + j;

    float zi = G[g]       + bias[j];
    float zo = G[g + 128] + bias[128 + j];
    float zu = G[g + 256] + bias[256 + j];
    float fc = 0.0f;

    if (!leaf) {
        float gf = G[g + 384] + bias[384 + j];
        const float* Ap = A + (size_t)p * ratio * 512 + j;
        const float* Cp = Cc + (size_t)p * ratio * 128 + j;
        for (int t = 0; t < ratio; ++t) {
            zi += Ap[0];
            zo += Ap[128];
            zu += Ap[256];
            float f = sigmoidf_(gf + Ap[384]);
            fc += f * Cp[0];
            Ap += 512;
            Cp += 128;
        }
    }

    float i = sigmoidf_(zi);
    float o = sigmoidf_(zo);
    float u = tanhf_(zu);
    float c = i * u + fc;
    Hout[(size_t)p * 128 + j] = o * tanhf_(c);
    Cout[(size_t)p * 128 + j] = c;
}

// ---------------------------------------------------------------------------
// output head: out[4096,4] = H_root @ W_out + b_out  (one warp per row)
// ---------------------------------------------------------------------------
__global__ void out_kernel(const float* __restrict__ H,
                           const float* __restrict__ Wout,
                           const float* __restrict__ bout,
                           float* __restrict__ out)
{
    int warp = (blockIdx.x * blockDim.x + threadIdx.x) >> 5;
    int lane = threadIdx.x & 31;
    const float* h = H + (size_t)warp * 128;

    float s0 = 0.f, s1 = 0.f, s2 = 0.f, s3 = 0.f;
#pragma unroll
    for (int k = lane; k < 128; k += 32) {
        float hv = h[k];
        float4 w = *reinterpret_cast<const float4*>(Wout + k * 4);
        s0 += hv * w.x; s1 += hv * w.y; s2 += hv * w.z; s3 += hv * w.w;
    }
#pragma unroll
    for (int off = 16; off; off >>= 1) {
        s0 += __shfl_xor_sync(0xffffffffu, s0, off);
        s1 += __shfl_xor_sync(0xffffffffu, s1, off);
        s2 += __shfl_xor_sync(0xffffffffu, s2, off);
        s3 += __shfl_xor_sync(0xffffffffu, s3, off);
    }
    if (lane == 0) {
        float4 v = make_float4(s0 + bout[0], s1 + bout[1], s2 + bout[2], s3 + bout[3]);
        *reinterpret_cast<float4*>(out + (size_t)warp * 4) = v;
    }
}

// ---------------------------------------------------------------------------
// launch
// ---------------------------------------------------------------------------
extern "C" void kernel_launch(void* const* d_in, const int* in_sizes, int n_in,
                              void* d_out, int out_size)
{
    const int*   sen = (const int*)d_in[0];
    const float* emb = (const float*)d_in[1];
    const float* W_ix = (const float*)d_in[2];
    const float* b_ix = (const float*)d_in[3];
    const float* W_ih = (const float*)d_in[4];
    const float* b_ih = (const float*)d_in[5];
    const float* W_fx = (const float*)d_in[6];
    const float* b_fx = (const float*)d_in[7];
    const float* W_fh = (const float*)d_in[8];
    const float* b_fh = (const float*)d_in[9];
    const float* W_ox = (const float*)d_in[10];
    const float* b_ox = (const float*)d_in[11];
    const float* W_oh = (const float*)d_in[12];
    const float* b_oh = (const float*)d_in[13];
    const float* W_ux = (const float*)d_in[14];
    const float* b_ux = (const float*)d_in[15];
    const float* W_uh = (const float*)d_in[16];
    const float* b_uh = (const float*)d_in[17];
    const float* W_out = (const float*)d_in[18];
    const float* b_out = (const float*)d_in[19];
    float* out = (float*)d_out;

    float *G, *A, *H, *C, *Wx, *Wh, *bias;
    cudaGetSymbolAddress((void**)&G, g_G);
    cudaGetSymbolAddress((void**)&A, g_A);
    cudaGetSymbolAddress((void**)&H, g_H);
    cudaGetSymbolAddress((void**)&C, g_C);
    cudaGetSymbolAddress((void**)&Wx, g_Wx);
    cudaGetSymbolAddress((void**)&Wh, g_Wh);
    cudaGetSymbolAddress((void**)&bias, g_bias);

    cudaFuncSetAttribute(gemm128<true>, cudaFuncAttributeMaxDynamicSharedMemorySize, SMEM_BYTES);
    cudaFuncSetAttribute(gemm128<false>, cudaFuncAttributeMaxDynamicSharedMemorySize, SMEM_BYTES);

    pack_weights<<<256, 256>>>(W_ix, W_ih, W_fx, W_fh, W_ox, W_oh, W_ux, W_uh,
                               b_ix, b_ih, b_fx, b_fh, b_ox, b_oh, b_ux, b_uh);

    static const int OFFH_[7] = {0, 4096, 20480, 86016, 217088, 479232, 741376};
    static const int LSH_[6]  = {4096, 16384, 65536, 131072, 262144, 262144};

    for (int L = 5; L >= 0; --L) {
        const int o0 = OFFH_[L];
        const int nL = LSH_[L];

        // G = gather(emb, sen) @ Wx4
        gemm128<true><<<dim3(nL / 128, 4), 256, SMEM_BYTES>>>(emb, sen + o0, Wx, G);

        if (L < 5) {
            const int c0 = OFFH_[L + 1];
            const int nC = LSH_[L + 1];
            // A = H_child @ Wh4
            gemm128<false><<<dim3(nC / 128, 4), 256, SMEM_BYTES>>>(
                H + (size_t)c0 * 128, nullptr, Wh, A);
            combine<<<nL / 2, 256>>>(G, A, C + (size_t)c0 * 128, bias,
                                     H + (size_t)o0 * 128, C + (size_t)o0 * 128,
                                     nC / nL, 0);
        } else {
            combine<<<nL / 2, 256>>>(G, nullptr, nullptr, bias,
                                     H + (size_t)o0 * 128, C + (size_t)o0 * 128,
                                     0, 1);
        }
    }

    out_kernel<<<4096 / 8, 256>>>(H, W_out, b_out, out);
}